// round 13
// baseline (speedup 1.0000x reference)
#include <cuda_runtime.h>
#include <cuda_bf16.h>
#include <cstdint>

// Inverted window cross-attention via warp-level bf16 mma.sync (sm_80+ ISA).
// R13 = R12 + ONE lever: occupancy 4->5 CTAs/SM via ROWB 144->128 (pad-free)
// with additive chunk swizzle P=(c+s(t&7))&7, s=[0,2,4,6,1,3,5,7], which keeps
// every ldmatrix (8 rows, fixed chunk) AND the loader STS.64 conflict-free.

typedef unsigned long long ull;

constexpr int Bc = 4, Hc = 128, Wc = 128, Cc = 192;
constexpr int Lc = Hc * Wc;
constexpr long long BLC = (long long)Bc * Lc * Cc;

constexpr int ROWB = 128;                 // bytes per row, no pad (swizzle handles banks)
constexpr int SQ2 = 0, SK2 = 8192, SK1 = 16384, SQ1 = 24576, SV = 32768;
constexpr int SMEM_TOTAL = 40960;

__device__ __forceinline__ uint32_t smem_u32(const void* p) {
    uint32_t a;
    asm("{ .reg .u64 t; cvta.to.shared.u64 t, %1; cvt.u32.u64 %0, t; }" : "=r"(a) : "l"(p));
    return a;
}
// additive chunk swizzle: s(t&7) = [0,2,4,6,1,3,5,7]
__device__ __forceinline__ int swz(int t) {
    return 2 * (t & 3) + ((t >> 2) & 1);
}
__device__ __forceinline__ uint32_t pack_bf16(float lo, float hi) {
    uint32_t r; asm("cvt.rn.bf16x2.f32 %0, %1, %2;" : "=r"(r) : "f"(hi), "f"(lo)); return r;
}
__device__ __forceinline__ float bf_lo(uint32_t p) { return __uint_as_float(p << 16); }
__device__ __forceinline__ float bf_hi(uint32_t p) { return __uint_as_float(p & 0xffff0000u); }

// split 4 floats -> hi uint2 + lo uint2 (bf16x2 each)
__device__ __forceinline__ void split4(float4 x, uint2& h, uint2& l) {
    uint32_t h0 = pack_bf16(x.x, x.y), h1 = pack_bf16(x.z, x.w);
    h = make_uint2(h0, h1);
    l = make_uint2(pack_bf16(x.x - bf_lo(h0), x.y - bf_hi(h0)),
                   pack_bf16(x.z - bf_lo(h1), x.w - bf_hi(h1)));
}

__device__ __forceinline__ void ldsm4(uint32_t* r, uint32_t a) {
    asm volatile("ldmatrix.sync.aligned.m8n8.x4.shared.b16 {%0,%1,%2,%3}, [%4];"
                 : "=r"(r[0]), "=r"(r[1]), "=r"(r[2]), "=r"(r[3]) : "r"(a));
}
__device__ __forceinline__ void ldsm4t(uint32_t* r, uint32_t a) {
    asm volatile("ldmatrix.sync.aligned.m8n8.x4.trans.shared.b16 {%0,%1,%2,%3}, [%4];"
                 : "=r"(r[0]), "=r"(r[1]), "=r"(r[2]), "=r"(r[3]) : "r"(a));
}
__device__ __forceinline__ void mma16816(float* d, const uint32_t* a, const uint32_t* b) {
    asm volatile("mma.sync.aligned.m16n8k16.row.col.f32.bf16.bf16.f32 "
                 "{%0,%1,%2,%3}, {%4,%5,%6,%7}, {%8,%9}, {%0,%1,%2,%3};"
                 : "+f"(d[0]), "+f"(d[1]), "+f"(d[2]), "+f"(d[3])
                 : "r"(a[0]), "r"(a[1]), "r"(a[2]), "r"(a[3]), "r"(b[0]), "r"(b[1]));
}

__global__ __launch_bounds__(128, 5)
void inv_attn_mma8(const float* __restrict__ qkv1,
                   const float* __restrict__ qkv2,
                   float* __restrict__ out)
{
    extern __shared__ char sm[];
    const int tid  = threadIdx.x;
    const int lane = tid & 31, wid = tid >> 5;

    const int win = blockIdx.x, head = blockIdx.y;
    const int b = win >> 8, hb = (win >> 4) & 15, wb = win & 15;
    const int row0  = hb * 8 * Wc + wb * 8;
    const int cbase = head * 32;

    // ------- loader: fully coalesced LDG (8 lanes x 16B per token line) ------
    {
        const int tg   = lane >> 3;          // token within 4-group
        const int fc   = lane & 7;           // 16B float chunk 0..7
        const int bc   = fc >> 1;            // bf16 chunk 0..3
        const int half = (fc & 1) * 8;       // 8B half within bf16 chunk
#pragma unroll
        for (int g = 0; g < 4; g++) {
            const int t = wid * 16 + 4 * g + tg;
            const int st = swz(t & 7);
            const int hoff = ((bc + st) & 7) * 16 + half;
            const int loff = ((bc + 4 + st) & 7) * 16 + half;
            const long long gt =
                ((long long)b * Lc + row0 + (t >> 3) * Wc + (t & 7)) * Cc + cbase + fc * 4;
            const int rb = t * ROWB;
            float4 x; uint2 h, l;
            // q2
            x = *(const float4*)(qkv2 + gt);
            split4(x, h, l);
            *(uint2*)(sm + SQ2 + rb + hoff) = h;  *(uint2*)(sm + SQ2 + rb + loff) = l;
            // k2
            x = *(const float4*)(qkv2 + BLC + gt);
            split4(x, h, l);
            *(uint2*)(sm + SK2 + rb + hoff) = h;  *(uint2*)(sm + SK2 + rb + loff) = l;
            // k1
            x = *(const float4*)(qkv1 + BLC + gt);
            split4(x, h, l);
            *(uint2*)(sm + SK1 + rb + hoff) = h;  *(uint2*)(sm + SK1 + rb + loff) = l;
            // q1
            x = *(const float4*)(qkv1 + gt);
            split4(x, h, l);
            *(uint2*)(sm + SQ1 + rb + hoff) = h;  *(uint2*)(sm + SQ1 + rb + loff) = l;
            // v1 + v2
            float4 p = *(const float4*)(qkv1 + 2 * BLC + gt);
            float4 q = *(const float4*)(qkv1 + 3 * BLC + gt);
            x = make_float4(p.x + q.x, p.y + q.y, p.z + q.z, p.w + q.w);
            split4(x, h, l);
            *(uint2*)(sm + SV + rb + hoff) = h;   *(uint2*)(sm + SV + rb + loff) = l;
        }
    }
    __syncthreads();

    const uint32_t smb = smem_u32(sm);
    const int mat = lane >> 3, li = lane & 7;
    const int r0 = wid * 16;
    const int fl = swz(li);                       // all ldsm rows satisfy row&7 == li

    // swizzled chunk offsets (bytes), hoisted per lane
    int aOffH[2], aOffL[2], bOff[2], vOff[4];
#pragma unroll
    for (int kc = 0; kc < 2; kc++) {
        aOffH[kc] = ((((mat >> 1) + 2 * kc) + fl) & 7) * 16;
        aOffL[kc] = ((((mat >> 1) + 2 * kc + 4) + fl) & 7) * 16;
        bOff[kc]  = ((((mat & 1) + 4 * (mat >> 1) + 2 * kc) + fl) & 7) * 16;
    }
#pragma unroll
    for (int t = 0; t < 4; t++)
        vOff[t] = (((4 * (mat >> 1) + t) + fl) & 7) * 16;

    const uint32_t aRow = (r0 + li + ((mat & 1) << 3)) * ROWB;
    const uint32_t bRow = li * ROWB;
    const uint32_t vRow = (li + ((mat & 1) << 3)) * ROWB;

    // ---------------- score MMAs ----------------
    uint32_t aQh[2][4], aQl[2][4], aKh[2][4], aKl[2][4];
#pragma unroll
    for (int kc = 0; kc < 2; kc++) {
        ldsm4(aQh[kc], smb + SQ2 + aRow + aOffH[kc]);
        ldsm4(aQl[kc], smb + SQ2 + aRow + aOffL[kc]);
        ldsm4(aKh[kc], smb + SK2 + aRow + aOffH[kc]);
        ldsm4(aKl[kc], smb + SK2 + aRow + aOffL[kc]);
    }
    float sacc[8][4] = {};
#pragma unroll
    for (int j = 0; j < 8; j++) {
#pragma unroll
        for (int kc = 0; kc < 2; kc++) {
            uint32_t bk[4], bq[4];
            const uint32_t off = bRow + j * 8 * ROWB + bOff[kc];
            ldsm4(bk, smb + SK1 + off);     // {k1h, k1l}
            ldsm4(bq, smb + SQ1 + off);     // {q1h, q1l}
            mma16816(sacc[j], aQh[kc], bk);
            mma16816(sacc[j], aQl[kc], bk);
            mma16816(sacc[j], aQh[kc], bk + 2);
            mma16816(sacc[j], aKh[kc], bq);
            mma16816(sacc[j], aKl[kc], bq);
            mma16816(sacc[j], aKh[kc], bq + 2);
        }
    }

    // ---------------- register softmax ----------------
    const float scale = 0.17677669529663687f;  // 32^-0.5
    float s0 = 0.f, s1 = 0.f;
#pragma unroll
    for (int j = 0; j < 8; j++) {
        sacc[j][0] = __expf(-scale * sacc[j][0]);
        sacc[j][1] = __expf(-scale * sacc[j][1]);
        sacc[j][2] = __expf(-scale * sacc[j][2]);
        sacc[j][3] = __expf(-scale * sacc[j][3]);
        s0 += sacc[j][0] + sacc[j][1];
        s1 += sacc[j][2] + sacc[j][3];
    }
    s0 += __shfl_xor_sync(0xffffffffu, s0, 1);
    s0 += __shfl_xor_sync(0xffffffffu, s0, 2);
    s1 += __shfl_xor_sync(0xffffffffu, s1, 1);
    s1 += __shfl_xor_sync(0xffffffffu, s1, 2);
    const float inv0 = 1.0f / s0, inv1 = 1.0f / s1;

    // ---------------- D-frag -> A-frag repack with bf16 split ----------------
    uint32_t ehi[4][4], elo[4][4];
#pragma unroll
    for (int kc = 0; kc < 4; kc++) {
        const float* t0 = sacc[2 * kc];
        const float* t1 = sacc[2 * kc + 1];
        uint32_t h;
        h = pack_bf16(t0[0], t0[1]); ehi[kc][0] = h;
        elo[kc][0] = pack_bf16(t0[0] - bf_lo(h), t0[1] - bf_hi(h));
        h = pack_bf16(t0[2], t0[3]); ehi[kc][1] = h;
        elo[kc][1] = pack_bf16(t0[2] - bf_lo(h), t0[3] - bf_hi(h));
        h = pack_bf16(t1[0], t1[1]); ehi[kc][2] = h;
        elo[kc][2] = pack_bf16(t1[0] - bf_lo(h), t1[1] - bf_hi(h));
        h = pack_bf16(t1[2], t1[3]); ehi[kc][3] = h;
        elo[kc][3] = pack_bf16(t1[2] - bf_lo(h), t1[3] - bf_hi(h));
    }

    // ---------------- PV MMAs ----------------
    float oacc[4][4] = {};
#pragma unroll
    for (int t = 0; t < 4; t++) {
#pragma unroll
        for (int kc = 0; kc < 4; kc++) {
            uint32_t bv[4];
            ldsm4t(bv, smb + SV + vRow + kc * 16 * ROWB + vOff[t]);  // {vh, vl}
            mma16816(oacc[t], ehi[kc], bv);
            mma16816(oacc[t], ehi[kc], bv + 2);
            mma16816(oacc[t], elo[kc], bv);
        }
    }

    // ---------------- output: shfl pair-exchange -> float4 stores ----------------
    {
        const int r  = lane >> 2;
        const int q  = lane & 3;
        const bool evn  = (q & 1) == 0;
        const int colb  = 4 * (q >> 1);
        const int n = r0 + r + (evn ? 0 : 8);
        const long long g =
            ((long long)b * Lc + row0 + (n >> 3) * Wc + (n & 7)) * Cc + cbase + colb;
#pragma unroll
        for (int t = 0; t < 4; t++) {
            const float m0 = oacc[t][0] * inv0, m1 = oacc[t][1] * inv0;
            const float m2 = oacc[t][2] * inv1, m3 = oacc[t][3] * inv1;
            const float pa = __shfl_xor_sync(0xffffffffu, evn ? m2 : m0, 1);
            const float pb = __shfl_xor_sync(0xffffffffu, evn ? m3 : m1, 1);
            const float4 o4 = evn ? make_float4(m0, m1, pa, pb)
                                  : make_float4(pa, pb, m2, m3);
            *(float4*)(out + g + 8 * t) = o4;
        }
    }
}

extern "C" void kernel_launch(void* const* d_in, const int* in_sizes, int n_in,
                              void* d_out, int out_size)
{
    const float* qkv1 = (const float*)d_in[0];
    const float* qkv2 = (const float*)d_in[1];
    float* out = (float*)d_out;

    cudaFuncSetAttribute(inv_attn_mma8,
                         cudaFuncAttributeMaxDynamicSharedMemorySize, SMEM_TOTAL);
    inv_attn_mma8<<<dim3(1024, 6, 1), 128, SMEM_TOTAL>>>(qkv1, qkv2, out);
}

// round 14
// speedup vs baseline: 1.0964x; 1.0964x over previous
#include <cuda_runtime.h>
#include <cuda_bf16.h>
#include <cstdint>

// Inverted window cross-attention via warp-level bf16 mma.sync (sm_80+ ISA).
// R14 = R12 + ONE change: double-buffered loader (all 6 LDG.128 of g+1 issued
// before converting/storing group g) to maximize memory-level parallelism.
// Same ROWB=144 swizzled tiles, same MMA/softmax/output as R12.

typedef unsigned long long ull;

constexpr int Bc = 4, Hc = 128, Wc = 128, Cc = 192;
constexpr int Lc = Hc * Wc;
constexpr long long BLC = (long long)Bc * Lc * Cc;

constexpr int ROWB = 144;                 // bytes per row (8 data chunks + 16B pad)
constexpr int SQ2 = 0, SK2 = 9216, SK1 = 18432, SQ1 = 27648, SV = 36864;
constexpr int SMEM_TOTAL = 46080;

__device__ __forceinline__ uint32_t smem_u32(const void* p) {
    uint32_t a;
    asm("{ .reg .u64 t; cvta.to.shared.u64 t, %1; cvt.u32.u64 %0, t; }" : "=r"(a) : "l"(p));
    return a;
}
// chunk swizzle: f(t&7) = [0,3,1,4,1,4,0,3]
__device__ __forceinline__ int swz(int t) {
    return 3 * (t & 1) + (((t >> 1) ^ (t >> 2)) & 1);
}
__device__ __forceinline__ uint32_t pack_bf16(float lo, float hi) {
    uint32_t r; asm("cvt.rn.bf16x2.f32 %0, %1, %2;" : "=r"(r) : "f"(hi), "f"(lo)); return r;
}
__device__ __forceinline__ float bf_lo(uint32_t p) { return __uint_as_float(p << 16); }
__device__ __forceinline__ float bf_hi(uint32_t p) { return __uint_as_float(p & 0xffff0000u); }

// split 4 floats -> hi uint2 + lo uint2 (bf16x2 each)
__device__ __forceinline__ void split4(float4 x, uint2& h, uint2& l) {
    uint32_t h0 = pack_bf16(x.x, x.y), h1 = pack_bf16(x.z, x.w);
    h = make_uint2(h0, h1);
    l = make_uint2(pack_bf16(x.x - bf_lo(h0), x.y - bf_hi(h0)),
                   pack_bf16(x.z - bf_lo(h1), x.w - bf_hi(h1)));
}

__device__ __forceinline__ void ldsm4(uint32_t* r, uint32_t a) {
    asm volatile("ldmatrix.sync.aligned.m8n8.x4.shared.b16 {%0,%1,%2,%3}, [%4];"
                 : "=r"(r[0]), "=r"(r[1]), "=r"(r[2]), "=r"(r[3]) : "r"(a));
}
__device__ __forceinline__ void ldsm4t(uint32_t* r, uint32_t a) {
    asm volatile("ldmatrix.sync.aligned.m8n8.x4.trans.shared.b16 {%0,%1,%2,%3}, [%4];"
                 : "=r"(r[0]), "=r"(r[1]), "=r"(r[2]), "=r"(r[3]) : "r"(a));
}
__device__ __forceinline__ void mma16816(float* d, const uint32_t* a, const uint32_t* b) {
    asm volatile("mma.sync.aligned.m16n8k16.row.col.f32.bf16.bf16.f32 "
                 "{%0,%1,%2,%3}, {%4,%5,%6,%7}, {%8,%9}, {%0,%1,%2,%3};"
                 : "+f"(d[0]), "+f"(d[1]), "+f"(d[2]), "+f"(d[3])
                 : "r"(a[0]), "r"(a[1]), "r"(a[2]), "r"(a[3]), "r"(b[0]), "r"(b[1]));
}

__global__ __launch_bounds__(128, 4)
void inv_attn_mma9(const float* __restrict__ qkv1,
                   const float* __restrict__ qkv2,
                   float* __restrict__ out)
{
    extern __shared__ char sm[];
    const int tid  = threadIdx.x;
    const int lane = tid & 31, wid = tid >> 5;

    const int win = blockIdx.x, head = blockIdx.y;
    const int b = win >> 8, hb = (win >> 4) & 15, wb = win & 15;
    const int row0  = hb * 8 * Wc + wb * 8;
    const int cbase = head * 32;

    // ------- loader: fully coalesced + double-buffered for MLP -------
    {
        const int tg   = lane >> 3;          // token within 4-group
        const int fc   = lane & 7;           // 16B float chunk 0..7
        const int bc   = fc >> 1;            // bf16 chunk 0..3
        const int half = (fc & 1) * 8;       // 8B half within bf16 chunk

        float4 buf[2][6];
        // prologue: issue all 6 LDGs of group 0
        {
            const int t = wid * 16 + tg;
            const long long gt =
                ((long long)b * Lc + row0 + (t >> 3) * Wc + (t & 7)) * Cc + cbase + fc * 4;
            buf[0][0] = *(const float4*)(qkv2 + gt);
            buf[0][1] = *(const float4*)(qkv2 + BLC + gt);
            buf[0][2] = *(const float4*)(qkv1 + BLC + gt);
            buf[0][3] = *(const float4*)(qkv1 + gt);
            buf[0][4] = *(const float4*)(qkv1 + 2 * BLC + gt);
            buf[0][5] = *(const float4*)(qkv1 + 3 * BLC + gt);
        }
#pragma unroll
        for (int g = 0; g < 4; g++) {
            // prefetch group g+1 before consuming group g
            if (g < 3) {
                const int t = wid * 16 + 4 * (g + 1) + tg;
                const long long gt =
                    ((long long)b * Lc + row0 + (t >> 3) * Wc + (t & 7)) * Cc + cbase + fc * 4;
                float4* nb = buf[(g + 1) & 1];
                nb[0] = *(const float4*)(qkv2 + gt);
                nb[1] = *(const float4*)(qkv2 + BLC + gt);
                nb[2] = *(const float4*)(qkv1 + BLC + gt);
                nb[3] = *(const float4*)(qkv1 + gt);
                nb[4] = *(const float4*)(qkv1 + 2 * BLC + gt);
                nb[5] = *(const float4*)(qkv1 + 3 * BLC + gt);
            }
            // convert + store group g
            const int t = wid * 16 + 4 * g + tg;
            const int ft = swz(t & 7);
            const int hoff = ((bc + ft) & 7) * 16 + half;
            const int loff = ((bc + 4 + ft) & 7) * 16 + half;
            const int rb = t * ROWB;
            const float4* cb = buf[g & 1];
            uint2 h, l;
            split4(cb[0], h, l);
            *(uint2*)(sm + SQ2 + rb + hoff) = h;  *(uint2*)(sm + SQ2 + rb + loff) = l;
            split4(cb[1], h, l);
            *(uint2*)(sm + SK2 + rb + hoff) = h;  *(uint2*)(sm + SK2 + rb + loff) = l;
            split4(cb[2], h, l);
            *(uint2*)(sm + SK1 + rb + hoff) = h;  *(uint2*)(sm + SK1 + rb + loff) = l;
            split4(cb[3], h, l);
            *(uint2*)(sm + SQ1 + rb + hoff) = h;  *(uint2*)(sm + SQ1 + rb + loff) = l;
            const float4 p = cb[4], q = cb[5];
            split4(make_float4(p.x + q.x, p.y + q.y, p.z + q.z, p.w + q.w), h, l);
            *(uint2*)(sm + SV + rb + hoff) = h;   *(uint2*)(sm + SV + rb + loff) = l;
        }
    }
    __syncthreads();

    const uint32_t smb = smem_u32(sm);
    const int mat = lane >> 3, li = lane & 7;
    const int r0 = wid * 16;
    const int fl = swz(li);                       // all ldsm rows satisfy row&7 == li

    // swizzled chunk offsets (bytes), hoisted per lane (R11/R12 verbatim)
    int aOffH[2], aOffL[2], bOff[2], vOff[4];
#pragma unroll
    for (int kc = 0; kc < 2; kc++) {
        aOffH[kc] = ((((mat >> 1) + 2 * kc) + fl) & 7) * 16;
        aOffL[kc] = ((((mat >> 1) + 2 * kc + 4) + fl) & 7) * 16;
        bOff[kc]  = ((((mat & 1) + 4 * (mat >> 1) + 2 * kc) + fl) & 7) * 16;
    }
#pragma unroll
    for (int t = 0; t < 4; t++)
        vOff[t] = (((4 * (mat >> 1) + t) + fl) & 7) * 16;

    const uint32_t aRow = (r0 + li + ((mat & 1) << 3)) * ROWB;
    const uint32_t bRow = li * ROWB;
    const uint32_t vRow = (li + ((mat & 1) << 3)) * ROWB;

    // ---------------- score MMAs (R12 verbatim) ----------------
    uint32_t aQh[2][4], aQl[2][4], aKh[2][4], aKl[2][4];
#pragma unroll
    for (int kc = 0; kc < 2; kc++) {
        ldsm4(aQh[kc], smb + SQ2 + aRow + aOffH[kc]);
        ldsm4(aQl[kc], smb + SQ2 + aRow + aOffL[kc]);
        ldsm4(aKh[kc], smb + SK2 + aRow + aOffH[kc]);
        ldsm4(aKl[kc], smb + SK2 + aRow + aOffL[kc]);
    }
    float sacc[8][4] = {};
#pragma unroll
    for (int j = 0; j < 8; j++) {
#pragma unroll
        for (int kc = 0; kc < 2; kc++) {
            uint32_t bk[4], bq[4];
            const uint32_t off = bRow + j * 8 * ROWB + bOff[kc];
            ldsm4(bk, smb + SK1 + off);     // {k1h, k1l}
            ldsm4(bq, smb + SQ1 + off);     // {q1h, q1l}
            mma16816(sacc[j], aQh[kc], bk);
            mma16816(sacc[j], aQl[kc], bk);
            mma16816(sacc[j], aQh[kc], bk + 2);
            mma16816(sacc[j], aKh[kc], bq);
            mma16816(sacc[j], aKl[kc], bq);
            mma16816(sacc[j], aKh[kc], bq + 2);
        }
    }

    // ---------------- register softmax (R12 verbatim) ----------------
    const float scale = 0.17677669529663687f;  // 32^-0.5
    float s0 = 0.f, s1 = 0.f;
#pragma unroll
    for (int j = 0; j < 8; j++) {
        sacc[j][0] = __expf(-scale * sacc[j][0]);
        sacc[j][1] = __expf(-scale * sacc[j][1]);
        sacc[j][2] = __expf(-scale * sacc[j][2]);
        sacc[j][3] = __expf(-scale * sacc[j][3]);
        s0 += sacc[j][0] + sacc[j][1];
        s1 += sacc[j][2] + sacc[j][3];
    }
    s0 += __shfl_xor_sync(0xffffffffu, s0, 1);
    s0 += __shfl_xor_sync(0xffffffffu, s0, 2);
    s1 += __shfl_xor_sync(0xffffffffu, s1, 1);
    s1 += __shfl_xor_sync(0xffffffffu, s1, 2);
    const float inv0 = 1.0f / s0, inv1 = 1.0f / s1;

    // ---------------- D-frag -> A-frag repack with bf16 split ----------------
    uint32_t ehi[4][4], elo[4][4];
#pragma unroll
    for (int kc = 0; kc < 4; kc++) {
        const float* t0 = sacc[2 * kc];
        const float* t1 = sacc[2 * kc + 1];
        uint32_t h;
        h = pack_bf16(t0[0], t0[1]); ehi[kc][0] = h;
        elo[kc][0] = pack_bf16(t0[0] - bf_lo(h), t0[1] - bf_hi(h));
        h = pack_bf16(t0[2], t0[3]); ehi[kc][1] = h;
        elo[kc][1] = pack_bf16(t0[2] - bf_lo(h), t0[3] - bf_hi(h));
        h = pack_bf16(t1[0], t1[1]); ehi[kc][2] = h;
        elo[kc][2] = pack_bf16(t1[0] - bf_lo(h), t1[1] - bf_hi(h));
        h = pack_bf16(t1[2], t1[3]); ehi[kc][3] = h;
        elo[kc][3] = pack_bf16(t1[2] - bf_lo(h), t1[3] - bf_hi(h));
    }

    // ---------------- PV MMAs (R12 verbatim) ----------------
    float oacc[4][4] = {};
#pragma unroll
    for (int t = 0; t < 4; t++) {
#pragma unroll
        for (int kc = 0; kc < 4; kc++) {
            uint32_t bv[4];
            ldsm4t(bv, smb + SV + vRow + kc * 16 * ROWB + vOff[t]);  // {vh, vl}
            mma16816(oacc[t], ehi[kc], bv);
            mma16816(oacc[t], ehi[kc], bv + 2);
            mma16816(oacc[t], elo[kc], bv);
        }
    }

    // ---------------- output: shfl pair-exchange -> float4 stores ----------------
    {
        const int r  = lane >> 2;
        const int q  = lane & 3;
        const bool evn  = (q & 1) == 0;
        const int colb  = 4 * (q >> 1);
        const int n = r0 + r + (evn ? 0 : 8);
        const long long g =
            ((long long)b * Lc + row0 + (n >> 3) * Wc + (n & 7)) * Cc + cbase + colb;
#pragma unroll
        for (int t = 0; t < 4; t++) {
            const float m0 = oacc[t][0] * inv0, m1 = oacc[t][1] * inv0;
            const float m2 = oacc[t][2] * inv1, m3 = oacc[t][3] * inv1;
            const float pa = __shfl_xor_sync(0xffffffffu, evn ? m2 : m0, 1);
            const float pb = __shfl_xor_sync(0xffffffffu, evn ? m3 : m1, 1);
            const float4 o4 = evn ? make_float4(m0, m1, pa, pb)
                                  : make_float4(pa, pb, m2, m3);
            *(float4*)(out + g + 8 * t) = o4;
        }
    }
}

extern "C" void kernel_launch(void* const* d_in, const int* in_sizes, int n_in,
                              void* d_out, int out_size)
{
    const float* qkv1 = (const float*)d_in[0];
    const float* qkv2 = (const float*)d_in[1];
    float* out = (float*)d_out;

    cudaFuncSetAttribute(inv_attn_mma9,
                         cudaFuncAttributeMaxDynamicSharedMemorySize, SMEM_TOTAL);
    inv_attn_mma9<<<dim3(1024, 6, 1), 128, SMEM_TOTAL>>>(qkv1, qkv2, out);
}

// round 15
// speedup vs baseline: 1.2688x; 1.1573x over previous
#include <cuda_runtime.h>
#include <cuda_bf16.h>
#include <cstdint>

// Inverted window cross-attention via warp-level bf16 mma.sync (sm_80+ ISA).
// R15 = R12 + ONE change: hoist half the PV ldmatrix loads (kc=0,1 for all t)
// to before the softmax, overlapping LDSM latency with the MUFU exp stretch.
// Loader, tiles (ROWB=144 swizzled), MMAs, softmax, output are R12-verbatim.

typedef unsigned long long ull;

constexpr int Bc = 4, Hc = 128, Wc = 128, Cc = 192;
constexpr int Lc = Hc * Wc;
constexpr long long BLC = (long long)Bc * Lc * Cc;

constexpr int ROWB = 144;                 // bytes per row (8 data chunks + 16B pad)
constexpr int SQ2 = 0, SK2 = 9216, SK1 = 18432, SQ1 = 27648, SV = 36864;
constexpr int SMEM_TOTAL = 46080;

__device__ __forceinline__ uint32_t smem_u32(const void* p) {
    uint32_t a;
    asm("{ .reg .u64 t; cvta.to.shared.u64 t, %1; cvt.u32.u64 %0, t; }" : "=r"(a) : "l"(p));
    return a;
}
// chunk swizzle: f(t&7) = [0,3,1,4,1,4,0,3]
__device__ __forceinline__ int swz(int t) {
    return 3 * (t & 1) + (((t >> 1) ^ (t >> 2)) & 1);
}
__device__ __forceinline__ uint32_t pack_bf16(float lo, float hi) {
    uint32_t r; asm("cvt.rn.bf16x2.f32 %0, %1, %2;" : "=r"(r) : "f"(hi), "f"(lo)); return r;
}
__device__ __forceinline__ float bf_lo(uint32_t p) { return __uint_as_float(p << 16); }
__device__ __forceinline__ float bf_hi(uint32_t p) { return __uint_as_float(p & 0xffff0000u); }

// split 4 floats -> hi uint2 + lo uint2 (bf16x2 each)
__device__ __forceinline__ void split4(float4 x, uint2& h, uint2& l) {
    uint32_t h0 = pack_bf16(x.x, x.y), h1 = pack_bf16(x.z, x.w);
    h = make_uint2(h0, h1);
    l = make_uint2(pack_bf16(x.x - bf_lo(h0), x.y - bf_hi(h0)),
                   pack_bf16(x.z - bf_lo(h1), x.w - bf_hi(h1)));
}

__device__ __forceinline__ void ldsm4(uint32_t* r, uint32_t a) {
    asm volatile("ldmatrix.sync.aligned.m8n8.x4.shared.b16 {%0,%1,%2,%3}, [%4];"
                 : "=r"(r[0]), "=r"(r[1]), "=r"(r[2]), "=r"(r[3]) : "r"(a));
}
__device__ __forceinline__ void ldsm4t(uint32_t* r, uint32_t a) {
    asm volatile("ldmatrix.sync.aligned.m8n8.x4.trans.shared.b16 {%0,%1,%2,%3}, [%4];"
                 : "=r"(r[0]), "=r"(r[1]), "=r"(r[2]), "=r"(r[3]) : "r"(a));
}
__device__ __forceinline__ void mma16816(float* d, const uint32_t* a, const uint32_t* b) {
    asm volatile("mma.sync.aligned.m16n8k16.row.col.f32.bf16.bf16.f32 "
                 "{%0,%1,%2,%3}, {%4,%5,%6,%7}, {%8,%9}, {%0,%1,%2,%3};"
                 : "+f"(d[0]), "+f"(d[1]), "+f"(d[2]), "+f"(d[3])
                 : "r"(a[0]), "r"(a[1]), "r"(a[2]), "r"(a[3]), "r"(b[0]), "r"(b[1]));
}

__global__ __launch_bounds__(128, 4)
void inv_attn_mma10(const float* __restrict__ qkv1,
                    const float* __restrict__ qkv2,
                    float* __restrict__ out)
{
    extern __shared__ char sm[];
    const int tid  = threadIdx.x;
    const int lane = tid & 31, wid = tid >> 5;

    const int win = blockIdx.x, head = blockIdx.y;
    const int b = win >> 8, hb = (win >> 4) & 15, wb = win & 15;
    const int row0  = hb * 8 * Wc + wb * 8;
    const int cbase = head * 32;

    // ------- loader (R12 verbatim): fully coalesced, 8 lanes x 16B per line ------
    {
        const int tg   = lane >> 3;          // token within 4-group
        const int fc   = lane & 7;           // 16B float chunk 0..7
        const int bc   = fc >> 1;            // bf16 chunk 0..3
        const int half = (fc & 1) * 8;       // 8B half within bf16 chunk
#pragma unroll
        for (int g = 0; g < 4; g++) {
            const int t = wid * 16 + 4 * g + tg;
            const int ft = swz(t & 7);
            const int hoff = ((bc + ft) & 7) * 16 + half;
            const int loff = ((bc + 4 + ft) & 7) * 16 + half;
            const long long gt =
                ((long long)b * Lc + row0 + (t >> 3) * Wc + (t & 7)) * Cc + cbase + fc * 4;
            const int rb = t * ROWB;
            float4 x; uint2 h, l;
            x = *(const float4*)(qkv2 + gt);
            split4(x, h, l);
            *(uint2*)(sm + SQ2 + rb + hoff) = h;  *(uint2*)(sm + SQ2 + rb + loff) = l;
            x = *(const float4*)(qkv2 + BLC + gt);
            split4(x, h, l);
            *(uint2*)(sm + SK2 + rb + hoff) = h;  *(uint2*)(sm + SK2 + rb + loff) = l;
            x = *(const float4*)(qkv1 + BLC + gt);
            split4(x, h, l);
            *(uint2*)(sm + SK1 + rb + hoff) = h;  *(uint2*)(sm + SK1 + rb + loff) = l;
            x = *(const float4*)(qkv1 + gt);
            split4(x, h, l);
            *(uint2*)(sm + SQ1 + rb + hoff) = h;  *(uint2*)(sm + SQ1 + rb + loff) = l;
            float4 p = *(const float4*)(qkv1 + 2 * BLC + gt);
            float4 q = *(const float4*)(qkv1 + 3 * BLC + gt);
            x = make_float4(p.x + q.x, p.y + q.y, p.z + q.z, p.w + q.w);
            split4(x, h, l);
            *(uint2*)(sm + SV + rb + hoff) = h;   *(uint2*)(sm + SV + rb + loff) = l;
        }
    }
    __syncthreads();

    const uint32_t smb = smem_u32(sm);
    const int mat = lane >> 3, li = lane & 7;
    const int r0 = wid * 16;
    const int fl = swz(li);

    // swizzled chunk offsets (bytes), hoisted per lane (R12 verbatim)
    int aOffH[2], aOffL[2], bOff[2], vOff[4];
#pragma unroll
    for (int kc = 0; kc < 2; kc++) {
        aOffH[kc] = ((((mat >> 1) + 2 * kc) + fl) & 7) * 16;
        aOffL[kc] = ((((mat >> 1) + 2 * kc + 4) + fl) & 7) * 16;
        bOff[kc]  = ((((mat & 1) + 4 * (mat >> 1) + 2 * kc) + fl) & 7) * 16;
    }
#pragma unroll
    for (int t = 0; t < 4; t++)
        vOff[t] = (((4 * (mat >> 1) + t) + fl) & 7) * 16;

    const uint32_t aRow = (r0 + li + ((mat & 1) << 3)) * ROWB;
    const uint32_t bRow = li * ROWB;
    const uint32_t vRow = (li + ((mat & 1) << 3)) * ROWB;

    // ---------------- score MMAs (R12 verbatim) ----------------
    uint32_t aQh[2][4], aQl[2][4], aKh[2][4], aKl[2][4];
#pragma unroll
    for (int kc = 0; kc < 2; kc++) {
        ldsm4(aQh[kc], smb + SQ2 + aRow + aOffH[kc]);
        ldsm4(aQl[kc], smb + SQ2 + aRow + aOffL[kc]);
        ldsm4(aKh[kc], smb + SK2 + aRow + aOffH[kc]);
        ldsm4(aKl[kc], smb + SK2 + aRow + aOffL[kc]);
    }
    float sacc[8][4] = {};
#pragma unroll
    for (int j = 0; j < 8; j++) {
#pragma unroll
        for (int kc = 0; kc < 2; kc++) {
            uint32_t bk[4], bq[4];
            const uint32_t off = bRow + j * 8 * ROWB + bOff[kc];
            ldsm4(bk, smb + SK1 + off);     // {k1h, k1l}
            ldsm4(bq, smb + SQ1 + off);     // {q1h, q1l}
            mma16816(sacc[j], aQh[kc], bk);
            mma16816(sacc[j], aQl[kc], bk);
            mma16816(sacc[j], aQh[kc], bk + 2);
            mma16816(sacc[j], aKh[kc], bq);
            mma16816(sacc[j], aKl[kc], bq);
            mma16816(sacc[j], aKh[kc], bq + 2);
        }
    }

    // ------- R15: prefetch V fragments for kc=0,1 (all t) before softmax -------
    uint32_t bvp[4][2][4];
#pragma unroll
    for (int t = 0; t < 4; t++)
#pragma unroll
        for (int kc = 0; kc < 2; kc++)
            ldsm4t(bvp[t][kc], smb + SV + vRow + kc * 16 * ROWB + vOff[t]);

    // ---------------- register softmax (R12 verbatim) ----------------
    const float scale = 0.17677669529663687f;  // 32^-0.5
    float s0 = 0.f, s1 = 0.f;
#pragma unroll
    for (int j = 0; j < 8; j++) {
        sacc[j][0] = __expf(-scale * sacc[j][0]);
        sacc[j][1] = __expf(-scale * sacc[j][1]);
        sacc[j][2] = __expf(-scale * sacc[j][2]);
        sacc[j][3] = __expf(-scale * sacc[j][3]);
        s0 += sacc[j][0] + sacc[j][1];
        s1 += sacc[j][2] + sacc[j][3];
    }
    s0 += __shfl_xor_sync(0xffffffffu, s0, 1);
    s0 += __shfl_xor_sync(0xffffffffu, s0, 2);
    s1 += __shfl_xor_sync(0xffffffffu, s1, 1);
    s1 += __shfl_xor_sync(0xffffffffu, s1, 2);
    const float inv0 = 1.0f / s0, inv1 = 1.0f / s1;

    // ---------------- D-frag -> A-frag repack with bf16 split ----------------
    uint32_t ehi[4][4], elo[4][4];
#pragma unroll
    for (int kc = 0; kc < 4; kc++) {
        const float* t0 = sacc[2 * kc];
        const float* t1 = sacc[2 * kc + 1];
        uint32_t h;
        h = pack_bf16(t0[0], t0[1]); ehi[kc][0] = h;
        elo[kc][0] = pack_bf16(t0[0] - bf_lo(h), t0[1] - bf_hi(h));
        h = pack_bf16(t0[2], t0[3]); ehi[kc][1] = h;
        elo[kc][1] = pack_bf16(t0[2] - bf_lo(h), t0[3] - bf_hi(h));
        h = pack_bf16(t1[0], t1[1]); ehi[kc][2] = h;
        elo[kc][2] = pack_bf16(t1[0] - bf_lo(h), t1[1] - bf_hi(h));
        h = pack_bf16(t1[2], t1[3]); ehi[kc][3] = h;
        elo[kc][3] = pack_bf16(t1[2] - bf_lo(h), t1[3] - bf_hi(h));
    }

    // ---------------- PV MMAs: kc 0,1 from prefetch; kc 2,3 inline ----------------
    float oacc[4][4] = {};
#pragma unroll
    for (int t = 0; t < 4; t++) {
#pragma unroll
        for (int kc = 0; kc < 2; kc++) {
            const uint32_t* bv = bvp[t][kc];
            mma16816(oacc[t], ehi[kc], bv);
            mma16816(oacc[t], ehi[kc], bv + 2);
            mma16816(oacc[t], elo[kc], bv);
        }
#pragma unroll
        for (int kc = 2; kc < 4; kc++) {
            uint32_t bv[4];
            ldsm4t(bv, smb + SV + vRow + kc * 16 * ROWB + vOff[t]);  // {vh, vl}
            mma16816(oacc[t], ehi[kc], bv);
            mma16816(oacc[t], ehi[kc], bv + 2);
            mma16816(oacc[t], elo[kc], bv);
        }
    }

    // ---------------- output: shfl pair-exchange -> float4 stores ----------------
    {
        const int r  = lane >> 2;
        const int q  = lane & 3;
        const bool evn  = (q & 1) == 0;
        const int colb  = 4 * (q >> 1);
        const int n = r0 + r + (evn ? 0 : 8);
        const long long g =
            ((long long)b * Lc + row0 + (n >> 3) * Wc + (n & 7)) * Cc + cbase + colb;
#pragma unroll
        for (int t = 0; t < 4; t++) {
            const float m0 = oacc[t][0] * inv0, m1 = oacc[t][1] * inv0;
            const float m2 = oacc[t][2] * inv1, m3 = oacc[t][3] * inv1;
            const float pa = __shfl_xor_sync(0xffffffffu, evn ? m2 : m0, 1);
            const float pb = __shfl_xor_sync(0xffffffffu, evn ? m3 : m1, 1);
            const float4 o4 = evn ? make_float4(m0, m1, pa, pb)
                                  : make_float4(pa, pb, m2, m3);
            *(float4*)(out + g + 8 * t) = o4;
        }
    }
}

extern "C" void kernel_launch(void* const* d_in, const int* in_sizes, int n_in,
                              void* d_out, int out_size)
{
    const float* qkv1 = (const float*)d_in[0];
    const float* qkv2 = (const float*)d_in[1];
    float* out = (float*)d_out;

    cudaFuncSetAttribute(inv_attn_mma10,
                         cudaFuncAttributeMaxDynamicSharedMemorySize, SMEM_TOTAL);
    inv_attn_mma10<<<dim3(1024, 6, 1), 128, SMEM_TOTAL>>>(qkv1, qkv2, out);
}